// round 16
// baseline (speedup 1.0000x reference)
#include <cuda_runtime.h>
#include <cuda_fp16.h>
#include <math.h>
#include <stdint.h>

#define KB_ 4
#define KT_ 4096
#define KDIM_ 64
#define KHID_ 256
#define KROWS_ (KB_ * KT_)   // 16384
#define HIST_ 128

// ---------------------------------------------------------------------------
// Scratch (device globals)
// ---------------------------------------------------------------------------
__device__ float g_h[KROWS_ * KHID_];
__device__ __half g_lnhi[KROWS_ * KHID_];
__device__ __half g_qkvhi[KROWS_ * 3 * KHID_];
__device__ __half g_qkvlo[KROWS_ * 3 * KHID_];
__device__ __half g_m1hi[KROWS_ * KHID_];
__device__ __half g_hshi[KROWS_ * KHID_];
__device__ __half g_xhi[KROWS_ * KDIM_];
#define OFF_IN_  0
#define OFF_QKV_ 16384
#define OFF_W1_  212992
#define OFF_W2_  278528
#define OFF_OUT_ 344064
#define WSPLIT_TOT_ 360448
#define XSPLIT_TOT_ (KROWS_ * KDIM_)
__device__ __half g_whi[WSPLIT_TOT_];
__device__ __half g_wlo[WSPLIT_TOT_];

// ---------------------------------------------------------------------------
// PTX helpers
// ---------------------------------------------------------------------------
__device__ __forceinline__ uint32_t smem_u32(const void* p) {
    uint32_t a;
    asm("{ .reg .u64 t; cvta.to.shared.u64 t, %1; cvt.u32.u64 %0, t; }"
        : "=r"(a) : "l"(p));
    return a;
}
__device__ __forceinline__ void ldsm4(uint32_t* r, uint32_t a) {
    asm volatile("ldmatrix.sync.aligned.m8n8.x4.shared.b16 {%0,%1,%2,%3}, [%4];"
        : "=r"(r[0]), "=r"(r[1]), "=r"(r[2]), "=r"(r[3]) : "r"(a));
}
__device__ __forceinline__ void ldsm4t(uint32_t* r, uint32_t a) {
    asm volatile("ldmatrix.sync.aligned.m8n8.x4.trans.shared.b16 {%0,%1,%2,%3}, [%4];"
        : "=r"(r[0]), "=r"(r[1]), "=r"(r[2]), "=r"(r[3]) : "r"(a));
}
__device__ __forceinline__ void mma_f16(float* d, const uint32_t* a,
                                        const uint32_t* b) {
    asm volatile(
        "mma.sync.aligned.m16n8k16.row.col.f32.f16.f16.f32 "
        "{%0,%1,%2,%3}, {%4,%5,%6,%7}, {%8,%9}, {%0,%1,%2,%3};"
        : "+f"(d[0]), "+f"(d[1]), "+f"(d[2]), "+f"(d[3])
        : "r"(a[0]), "r"(a[1]), "r"(a[2]), "r"(a[3]), "r"(b[0]), "r"(b[1]));
}
__device__ __forceinline__ uint32_t sw128(uint32_t off) {
    return off ^ ((off >> 3) & 0x70);
}
__device__ __forceinline__ void cp16(uint32_t smaddr, const void* g) {
    asm volatile("cp.async.cg.shared.global [%0], [%1], 16;"
                 :: "r"(smaddr), "l"(g) : "memory");
}
__device__ __forceinline__ void cp_commit() {
    asm volatile("cp.async.commit_group;" ::: "memory");
}
__device__ __forceinline__ void cp_wait0() {
    asm volatile("cp.async.wait_group 0;" ::: "memory");
}

// ---------------------------------------------------------------------------
// Merged split: 5 weights (transposed, hi+lo) + x (plain, hi only)
// ---------------------------------------------------------------------------
__global__ __launch_bounds__(256)
void wsplit_all(const float* __restrict__ x, const float* __restrict__ W_in,
                const float* __restrict__ W_qkv, const float* __restrict__ W1,
                const float* __restrict__ W2, const float* __restrict__ W_out,
                __half* __restrict__ whi, __half* __restrict__ wlo,
                __half* __restrict__ xhi)
{
    const int idx = blockIdx.x * 256 + threadIdx.x;
    if (idx >= WSPLIT_TOT_ + XSPLIT_TOT_) return;
    if (idx >= WSPLIT_TOT_) {
        const int i = idx - WSPLIT_TOT_;
        xhi[i] = __float2half_rn(x[i]);
        return;
    }
    const float* src;
    int off, N, K, local;
    if (idx < 16384)       { src = W_in;  off = OFF_IN_;  K = 64;  N = 256; local = idx; }
    else if (idx < 212992) { src = W_qkv; off = OFF_QKV_; K = 256; N = 768; local = idx - 16384; }
    else if (idx < 278528) { src = W1;    off = OFF_W1_;  K = 256; N = 256; local = idx - 212992; }
    else if (idx < 344064) { src = W2;    off = OFF_W2_;  K = 256; N = 256; local = idx - 278528; }
    else                   { src = W_out; off = OFF_OUT_; K = 256; N = 64;  local = idx - 344064; }
    const int k = local / N, n = local % N;
    const float a = src[local];
    const __half h = __float2half_rn(a);
    whi[off + (size_t)n * K + k] = h;
    wlo[off + (size_t)n * K + k] = __float2half_rn(a - __half2float(h));
}

// ---------------------------------------------------------------------------
// HMMA GEMM fp16 2-product, single sync/chunk, 2 buffers, 3 CTAs/SM target.
// EPI: 0 bias->fp32 | 1 bias+gelu->hi | 2 bias+res->fp32+hi | 3 bias->hi+lo
// EPI==3: lo written only for n0 >= KHID_ (K/V columns)
// ---------------------------------------------------------------------------
#define GEMM_STAGE_ 32768
#define GEMM_SMEM_  (2 * GEMM_STAGE_)

__device__ __forceinline__ void gemm_stage_chunk(
    uint32_t sbst, const __half* Ahi,
    const __half* Bhi, const __half* Blo,
    int m0, int n0, int c, int K, int tid)
{
    constexpr uint32_t A_HI = 0, B_HI = 16384, B_LO = 24576;
#pragma unroll
    for (int i = 0; i < 4; i++) {
        const int u = i * 256 + tid;
        const int row = u >> 3, seg = u & 7;
        const uint32_t sw = sw128(row * 128 + seg * 16);
        cp16(sbst + A_HI + sw, &Ahi[(size_t)(m0 + row) * K + c * 64 + seg * 8]);
    }
#pragma unroll
    for (int i = 0; i < 2; i++) {
        const int u = i * 256 + tid;
        const int row = u >> 3, seg = u & 7;
        const uint32_t sw = sw128(row * 128 + seg * 16);
        const size_t gsrc = (size_t)(n0 + row) * K + c * 64 + seg * 8;
        cp16(sbst + B_HI + sw, &Bhi[gsrc]);
        cp16(sbst + B_LO + sw, &Blo[gsrc]);
    }
}

template <int EPI>
__global__ __launch_bounds__(256, 3)
void gemm_mma(const __half* __restrict__ Ahi,
              const __half* __restrict__ Bhi, const __half* __restrict__ Blo,
              const float* __restrict__ bias, const float* __restrict__ res,
              float* __restrict__ out,
              __half* __restrict__ outhi, __half* __restrict__ outlo,
              int M, int K, int N)
{
    extern __shared__ char smp[];
    const uint32_t sb = smem_u32(smp);
    constexpr uint32_t A_HI = 0, B_HI = 16384, B_LO = 24576;

    const int tid = threadIdx.x, lane = tid & 31, w = tid >> 5;
    const int wm = w & 3, wn = w >> 2;
    const int m0 = blockIdx.y * 128, n0 = blockIdx.x * 64;

    float acc[2][4][4];
#pragma unroll
    for (int mi = 0; mi < 2; mi++)
#pragma unroll
        for (int ni = 0; ni < 4; ni++)
#pragma unroll
            for (int e = 0; e < 4; e++) acc[mi][ni][e] = 0.f;

    const int a_row_l  = lane & 15;
    const int a_kseg_l = lane >> 4;
    const int b_row_l  = ((lane >> 4) << 3) + (lane & 7);
    const int b_kseg_l = (lane >> 3) & 1;

    const int nchunks = K >> 6;

    gemm_stage_chunk(sb, Ahi, Bhi, Blo, m0, n0, 0, K, tid);
    cp_commit();

    for (int c = 0; c < nchunks; c++) {
        const uint32_t cur = sb + (uint32_t)(c & 1) * GEMM_STAGE_;
        cp_wait0();
        __syncthreads();
        if (c + 1 < nchunks) {
            gemm_stage_chunk(sb + (uint32_t)((c + 1) & 1) * GEMM_STAGE_,
                             Ahi, Bhi, Blo, m0, n0, c + 1, K, tid);
            cp_commit();
        }

#pragma unroll
        for (int ks = 0; ks < 4; ks++) {
            uint32_t ah[2][4], bh[4][2], bl[4][2];
#pragma unroll
            for (int mi = 0; mi < 2; mi++) {
                const int row = wm * 32 + mi * 16 + a_row_l;
                const uint32_t sw = sw128(row * 128 + (ks * 2 + a_kseg_l) * 16);
                ldsm4(ah[mi], cur + A_HI + sw);
            }
#pragma unroll
            for (int np = 0; np < 2; np++) {
                const int row = wn * 32 + np * 16 + b_row_l;
                const uint32_t sw = sw128(row * 128 + (ks * 2 + b_kseg_l) * 16);
                uint32_t t[4];
                ldsm4(t, cur + B_HI + sw);
                bh[np * 2][0] = t[0]; bh[np * 2][1] = t[1];
                bh[np * 2 + 1][0] = t[2]; bh[np * 2 + 1][1] = t[3];
                ldsm4(t, cur + B_LO + sw);
                bl[np * 2][0] = t[0]; bl[np * 2][1] = t[1];
                bl[np * 2 + 1][0] = t[2]; bl[np * 2 + 1][1] = t[3];
            }
#pragma unroll
            for (int mi = 0; mi < 2; mi++)
#pragma unroll
                for (int ni = 0; ni < 4; ni++)
                    mma_f16(acc[mi][ni], ah[mi], bh[ni]);
#pragma unroll
            for (int mi = 0; mi < 2; mi++)
#pragma unroll
                for (int ni = 0; ni < 4; ni++)
                    mma_f16(acc[mi][ni], ah[mi], bl[ni]);
        }
    }

    // ---- epilogue ----
    const int qrow = lane >> 2;
    const int qcol = 2 * (lane & 3);
    const bool write_lo = (EPI == 3) && (n0 >= KHID_);
#pragma unroll
    for (int mi = 0; mi < 2; mi++) {
#pragma unroll
        for (int ni = 0; ni < 4; ni++) {
            const int n = n0 + wn * 32 + ni * 8 + qcol;
            const float2 bv = *(const float2*)&bias[n];
#pragma unroll
            for (int hh = 0; hh < 2; hh++) {
                const int m = m0 + wm * 32 + mi * 16 + qrow + hh * 8;
                float2 v = make_float2(acc[mi][ni][2 * hh] + bv.x,
                                       acc[mi][ni][2 * hh + 1] + bv.y);
                if (EPI == 1) {
                    v.x = 0.5f * v.x * (1.f + erff(v.x * 0.70710678118654752f));
                    v.y = 0.5f * v.y * (1.f + erff(v.y * 0.70710678118654752f));
                }
                if (EPI == 2) {
                    float2 r = *(const float2*)&res[(size_t)m * N + n];
                    v.x += r.x; v.y += r.y;
                }
                if (EPI == 0 || EPI == 2)
                    *(float2*)&out[(size_t)m * N + n] = v;
                if (EPI != 0) {
                    __half2 h2 = __floats2half2_rn(v.x, v.y);
                    *(__half2*)&outhi[(size_t)m * N + n] = h2;
                    if (write_lo) {
                        const float rx = v.x - __half2float(__low2half(h2));
                        const float ry = v.y - __half2float(__high2half(h2));
                        *(__half2*)&outlo[(size_t)m * N + n] =
                            __floats2half2_rn(rx, ry);
                    }
                }
            }
        }
    }
}

// ---------------------------------------------------------------------------
// LayerNorm: one warp per row; outputs fp16 hi only
// ---------------------------------------------------------------------------
__global__ __launch_bounds__(256)
void ln_k(const float* __restrict__ x, const float* __restrict__ g,
          const float* __restrict__ b, __half* __restrict__ yhi)
{
    const int wid = threadIdx.x >> 5;
    const int lane = threadIdx.x & 31;
    const int row = blockIdx.x * 8 + wid;
    const float* xr = x + (size_t)row * KHID_;

    float v[8];
    float s = 0.f, s2 = 0.f;
#pragma unroll
    for (int i = 0; i < 8; i++) {
        v[i] = xr[lane + 32 * i];
        s += v[i];
        s2 += v[i] * v[i];
    }
#pragma unroll
    for (int o = 16; o; o >>= 1) {
        s += __shfl_xor_sync(0xffffffffu, s, o);
        s2 += __shfl_xor_sync(0xffffffffu, s2, o);
    }
    const float mu = s * (1.f / 256.f);
    const float var = s2 * (1.f / 256.f) - mu * mu;
    const float r = rsqrtf(var + 1e-5f);
#pragma unroll
    for (int i = 0; i < 8; i++) {
        const int d = lane + 32 * i;
        yhi[(size_t)row * KHID_ + d] =
            __float2half_rn((v[i] - mu) * r * g[d] + b[d]);
    }
}

// ---------------------------------------------------------------------------
// HMMA windowed attention, fp16 2-product (R15 structure, proven 147.6)
// ---------------------------------------------------------------------------
#define ATTN_SMEM_BYTES 115712

__device__ __forceinline__ void attn_stage_q(
    uint32_t dst, const __half* qhi, int g0, int c, int tid)
{
#pragma unroll
    for (int i = 0; i < 2; i++) {
        const int u = i * 256 + tid;
        const int row = u >> 3, seg = u & 7;
        const uint32_t sw = sw128(row * 128 + seg * 16);
        cp16(dst + sw, &qhi[(size_t)(g0 + row) * 768 + c * 64 + seg * 8]);
    }
}
__device__ __forceinline__ void attn_stage_k(
    uint32_t dst_hi, const __half* qhi, const __half* qlo,
    int kg0, int c, int tid)
{
#pragma unroll
    for (int i = 0; i < 2; i++) {
        const int u = i * 256 + tid;
        const int row = u >> 3, seg = u & 7;
        const uint32_t sw = sw128(row * 128 + seg * 16);
        const size_t gsrc = (size_t)(kg0 + row) * 768 + 256 + c * 64 + seg * 8;
        cp16(dst_hi + sw, &qhi[gsrc]);
        cp16(dst_hi + 8192 + sw, &qlo[gsrc]);
    }
}
__device__ __forceinline__ void attn_stage_v(
    uint32_t vb, const __half* qhi, const __half* qlo,
    int kg0, int half, int tid)
{
#pragma unroll
    for (int i = 0; i < 4; i++) {
        const int u = i * 256 + tid;
        const int row = u >> 4, seg = u & 15;
        const int panel = seg >> 3, sp = seg & 7;
        const uint32_t sw = panel * 8192 + sw128(row * 128 + sp * 16);
        const size_t gsrc = (size_t)(kg0 + row) * 768 + 512 + half * 128 + seg * 8;
        cp16(vb + sw, &qhi[gsrc]);
        cp16(vb + 16384 + sw, &qlo[gsrc]);
    }
}

__global__ __launch_bounds__(256)
void attn_k(const __half* __restrict__ qhi, const __half* __restrict__ qlo,
            float* __restrict__ h)
{
    extern __shared__ char smp[];
    const uint32_t sb = smem_u32(smp);
    constexpr uint32_t P_HI = 0, VB_ = 49152;
    float* redm = (float*)(smp + 114688);
    float* reds = (float*)(smp + 115200);

    const int tid = threadIdx.x, lane = tid & 31, w = tid >> 5;
    const int b  = blockIdx.x >> 6;
    const int qt = blockIdx.x & 63;
    const int t0 = qt * 64;
    const int g0 = b * KT_ + t0;
    const int kstart = (t0 >= HIST_) ? (t0 - HIST_) : 0;
    const int ntiles = (t0 + 64 - kstart) >> 6;
    const float scale = 0.0625f;

    const int wm = w & 3, wn = w >> 2;
    const int a_row_l  = lane & 15;
    const int a_kseg_l = lane >> 4;
    const int b_row_l  = ((lane >> 4) << 3) + (lane & 7);
    const int b_kseg_l = (lane >> 3) & 1;

    float sreg[3][4][4];
#pragma unroll
    for (int kt = 0; kt < 3; kt++)
#pragma unroll
        for (int ni = 0; ni < 4; ni++)
#pragma unroll
            for (int e = 0; e < 4; e++) sreg[kt][ni][e] = 0.f;

    attn_stage_q(sb + 0, qhi, g0, 0, tid);
    attn_stage_k(sb + 16384, qhi, qlo, b * KT_ + kstart, 0, tid);
    cp_commit();

    uint32_t kpar = 0;
    for (int c = 0; c < 4; c++) {
#pragma unroll
        for (int kt = 0; kt < 3; kt++) {
            if (kt < ntiles) {
                cp_wait0();
                __syncthreads();
                {
                    const int nkt = (kt + 1 < ntiles) ? kt + 1 : 0;
                    const int nc  = (kt + 1 < ntiles) ? c : c + 1;
                    if (nc < 4) {
                        attn_stage_k(sb + 16384 + (kpar ^ 1u) * 16384,
                                     qhi, qlo, b * KT_ + kstart + nkt * 64, nc, tid);
                        if (nkt == 0)
                            attn_stage_q(sb + (uint32_t)(nc & 1) * 8192,
                                         qhi, g0, nc, tid);
                        cp_commit();
                    }
                }
                const uint32_t qb = sb + (uint32_t)(c & 1) * 8192;
                const uint32_t kb = sb + 16384 + kpar * 16384;
#pragma unroll
                for (int ks = 0; ks < 4; ks++) {
                    uint32_t qh[4], kh[4][2], kl[4][2];
                    {
                        const int row = wm * 16 + a_row_l;
                        const uint32_t sw = sw128(row * 128 + (ks * 2 + a_kseg_l) * 16);
                        ldsm4(qh, qb + sw);
                    }
#pragma unroll
                    for (int np = 0; np < 2; np++) {
                        const int row = wn * 32 + np * 16 + b_row_l;
                        const uint32_t sw = sw128(row * 128 + (ks * 2 + b_kseg_l) * 16);
                        uint32_t t[4];
                        ldsm4(t, kb + sw);
                        kh[np * 2][0] = t[0]; kh[np * 2][1] = t[1];
                        kh[np * 2 + 1][0] = t[2]; kh[np * 2 + 1][1] = t[3];
                        ldsm4(t, kb + 8192 + sw);
                        kl[np * 2][0] = t[0]; kl[np * 2][1] = t[1];
                        kl[np * 2 + 1][0] = t[2]; kl[np * 2 + 1][1] = t[3];
                    }
#pragma unroll
                    for (int ni = 0; ni < 4; ni++)
                        mma_f16(sreg[kt][ni], qh, kh[ni]);
#pragma unroll
                    for (int ni = 0; ni < 4; ni++)
                        mma_f16(sreg[kt][ni], qh, kl[ni]);
                }
                kpar ^= 1u;
            }
        }
    }

    const int qr0 = wm * 16 + (lane >> 2);
#pragma unroll
    for (int kt = 0; kt < 3; kt++)
        if (kt < ntiles)
#pragma unroll
            for (int ni = 0; ni < 4; ni++)
#pragma unroll
                for (int e = 0; e < 4; e++) {
                    const int qrow = t0 + qr0 + 8 * (e >> 1);
                    const int key = kstart + kt * 64 + wn * 32 + ni * 8 + (lane & 3) * 2 + (e & 1);
                    const int d = qrow - key;
                    sreg[kt][ni][e] = (d >= 0 && d <= HIST_)
                                      ? sreg[kt][ni][e] * scale : -3.0e38f;
                }

    float mx[2] = {-3.0e38f, -3.0e38f};
#pragma unroll
    for (int kt = 0; kt < 3; kt++)
        if (kt < ntiles)
#pragma unroll
            for (int ni = 0; ni < 4; ni++)
#pragma unroll
                for (int e = 0; e < 4; e++)
                    mx[e >> 1] = fmaxf(mx[e >> 1], sreg[kt][ni][e]);
#pragma unroll
    for (int o = 1; o <= 2; o <<= 1) {
        mx[0] = fmaxf(mx[0], __shfl_xor_sync(0xffffffffu, mx[0], o));
        mx[1] = fmaxf(mx[1], __shfl_xor_sync(0xffffffffu, mx[1], o));
    }
    if ((lane & 3) == 0) {
        redm[qr0 * 2 + wn] = mx[0];
        redm[(qr0 + 8) * 2 + wn] = mx[1];
    }
    __syncthreads();
    attn_stage_v(sb + VB_, qhi, qlo, b * KT_ + kstart, 0, tid);
    cp_commit();

    const float M0 = fmaxf(redm[qr0 * 2], redm[qr0 * 2 + 1]);
    const float M1 = fmaxf(redm[(qr0 + 8) * 2], redm[(qr0 + 8) * 2 + 1]);
    float sum[2] = {0.f, 0.f};
#pragma unroll
    for (int kt = 0; kt < 3; kt++)
        if (kt < ntiles)
#pragma unroll
            for (int ni = 0; ni < 4; ni++)
#pragma unroll
                for (int e = 0; e < 4; e++) {
                    const float ex = __expf(sreg[kt][ni][e] - ((e >> 1) ? M1 : M0));
                    sreg[kt][ni][e] = ex;
                    sum[e >> 1] += ex;
                }
#pragma unroll
    for (int o = 1; o <= 2; o <<= 1) {
        sum[0] += __shfl_xor_sync(0xffffffffu, sum[0], o);
        sum[1] += __shfl_xor_sync(0xffffffffu, sum[1], o);
    }
    if ((lane & 3) == 0) {
        reds[qr0 * 2 + wn] = sum[0];
        reds[(qr0 + 8) * 2 + wn] = sum[1];
    }
    __syncthreads();
    const float R0 = 1.f / (reds[qr0 * 2] + reds[qr0 * 2 + 1]);
    const float R1 = 1.f / (reds[(qr0 + 8) * 2] + reds[(qr0 + 8) * 2 + 1]);

#pragma unroll
    for (int kt = 0; kt < 3; kt++)
        if (kt < ntiles)
#pragma unroll
            for (int ni = 0; ni < 4; ni++)
#pragma unroll
                for (int hh = 0; hh < 2; hh++) {
                    const float rv = hh ? R1 : R0;
                    const float p0 = sreg[kt][ni][2 * hh] * rv;
                    const float p1 = sreg[kt][ni][2 * hh + 1] * rv;
                    const int row = qr0 + 8 * hh;
                    const int col = wn * 32 + ni * 8 + (lane & 3) * 2;
                    const uint32_t sw = sw128(row * 128 + col * 2);
                    *(__half2*)(smp + P_HI + kt * 8192 + sw) =
                        __floats2half2_rn(p0, p1);
                }

    const int wm2 = w & 1, wn2 = w >> 1;
    const int R = 2 * ntiles;
    float o[2][4][4];

    for (int r = 0; r < R; r++) {
        const int half = (r < ntiles) ? 0 : 1;
        const int kt   = (r < ntiles) ? r : r - ntiles;
        const uint32_t vb = sb + VB_ + (uint32_t)(r & 1) * 32768;

        cp_wait0();
        __syncthreads();
        if (r + 1 < R) {
            const int nh = (r + 1 < ntiles) ? 0 : 1;
            const int nk = (r + 1 < ntiles) ? r + 1 : r + 1 - ntiles;
            attn_stage_v(sb + VB_ + (uint32_t)((r + 1) & 1) * 32768,
                         qhi, qlo, b * KT_ + kstart + nk * 64, nh, tid);
            cp_commit();
        }

        if (kt == 0) {
#pragma unroll
            for (int mi = 0; mi < 2; mi++)
#pragma unroll
                for (int ni = 0; ni < 4; ni++)
#pragma unroll
                    for (int e = 0; e < 4; e++) o[mi][ni][e] = 0.f;
        }

#pragma unroll
        for (int ks = 0; ks < 4; ks++) {
            uint32_t ph[2][4], vh[4][2], vl[4][2];
#pragma unroll
            for (int mi = 0; mi < 2; mi++) {
                const int row = wm2 * 32 + mi * 16 + a_row_l;
                const uint32_t sw = sw128(row * 128 + (ks * 2 + a_kseg_l) * 16);
                ldsm4(ph[mi], sb + P_HI + kt * 8192 + sw);
            }
#pragma unroll
            for (int g = 0; g < 2; g++) {
                const int dcol = wn2 * 32 + g * 16 + (lane >> 4) * 8;
                const int key = ks * 16 + (lane & 7) + ((lane >> 3) & 1) * 8;
                const int panel = dcol >> 6;
                const uint32_t sw =
                    panel * 8192 + sw128(key * 128 + (dcol & 63) * 2);
                uint32_t t[4];
                ldsm4t(t, vb + sw);
                vh[g * 2][0] = t[0]; vh[g * 2][1] = t[1];
                vh[g * 2 + 1][0] = t[2]; vh[g * 2 + 1][1] = t[3];
                ldsm4t(t, vb + 16384 + sw);
                vl[g * 2][0] = t[0]; vl[g * 2][1] = t[1];
                vl[g * 2 + 1][0] = t[2]; vl[g * 2 + 1][1] = t[3];
            }
#pragma unroll
            for (int mi = 0; mi < 2; mi++)
#pragma unroll
                for (int ni = 0; ni < 4; ni++)
                    mma_f16(o[mi][ni], ph[mi], vh[ni]);
#pragma unroll
            for (int mi = 0; mi < 2; mi++)
#pragma unroll
                for (int ni = 0; ni < 4; ni++)
                    mma_f16(o[mi][ni], ph[mi], vl[ni]);
        }

        if (kt == ntiles - 1) {
#pragma unroll
            for (int mi = 0; mi < 2; mi++)
#pragma unroll
                for (int ni = 0; ni < 4; ni++) {
                    const int col = half * 128 + wn2 * 32 + ni * 8 + (lane & 3) * 2;
#pragma unroll
                    for (int hh = 0; hh < 2; hh++) {
                        const int row = wm2 * 32 + mi * 16 + (lane >> 2) + 8 * hh;
                        float2 hv = *(const float2*)&h[(size_t)(g0 + row) * KHID_ + col];
                        hv.x += o[mi][ni][2 * hh];
                        hv.y += o[mi][ni][2 * hh + 1];
                        *(float2*)&h[(size_t)(g0 + row) * KHID_ + col] = hv;
                    }
                }
        }
    }
}

// ---------------------------------------------------------------------------
// Launch
// ---------------------------------------------------------------------------
extern "C" void kernel_launch(void* const* d_in, const int* in_sizes, int n_in,
                              void* d_out, int out_size)
{
    (void)in_sizes; (void)n_in; (void)out_size;
    const float* x       = (const float*)d_in[0];
    const float* W_in    = (const float*)d_in[1];
    const float* b_in    = (const float*)d_in[2];
    const float* W_qkv   = (const float*)d_in[3];
    const float* b_qkv   = (const float*)d_in[4];
    const float* g_attn  = (const float*)d_in[5];
    const float* be_attn = (const float*)d_in[6];
    const float* g_mlp   = (const float*)d_in[7];
    const float* be_mlp  = (const float*)d_in[8];
    const float* W1      = (const float*)d_in[9];
    const float* b1      = (const float*)d_in[10];
    const float* W2      = (const float*)d_in[11];
    const float* b2      = (const float*)d_in[12];
    const float* W_out   = (const float*)d_in[13];
    const float* b_out   = (const float*)d_in[14];
    float* out = (float*)d_out;

    float* h_p;
    __half *whi, *wlo, *xhi, *lnhi, *qhi, *qlo, *m1hi, *hshi;
    cudaGetSymbolAddress((void**)&h_p, g_h);
    cudaGetSymbolAddress((void**)&whi, g_whi);
    cudaGetSymbolAddress((void**)&wlo, g_wlo);
    cudaGetSymbolAddress((void**)&xhi, g_xhi);
    cudaGetSymbolAddress((void**)&lnhi, g_lnhi);
    cudaGetSymbolAddress((void**)&qhi, g_qkvhi);
    cudaGetSymbolAddress((void**)&qlo, g_qkvlo);
    cudaGetSymbolAddress((void**)&m1hi, g_m1hi);
    cudaGetSymbolAddress((void**)&hshi, g_hshi);

    cudaFuncSetAttribute((const void*)attn_k,
                         cudaFuncAttributeMaxDynamicSharedMemorySize, ATTN_SMEM_BYTES);
    cudaFuncSetAttribute((const void*)gemm_mma<0>,
                         cudaFuncAttributeMaxDynamicSharedMemorySize, GEMM_SMEM_);
    cudaFuncSetAttribute((const void*)gemm_mma<1>,
                         cudaFuncAttributeMaxDynamicSharedMemorySize, GEMM_SMEM_);
    cudaFuncSetAttribute((const void*)gemm_mma<2>,
                         cudaFuncAttributeMaxDynamicSharedMemorySize, GEMM_SMEM_);
    cudaFuncSetAttribute((const void*)gemm_mma<3>,
                         cudaFuncAttributeMaxDynamicSharedMemorySize, GEMM_SMEM_);

    const dim3 blk(256);

    // 0) split everything once
    wsplit_all<<<(WSPLIT_TOT_ + XSPLIT_TOT_ + 255) / 256, blk>>>(
        x, W_in, W_qkv, W1, W2, W_out, whi, wlo, xhi);

    // 1) h = x @ W_in + b_in
    gemm_mma<0><<<dim3(4, 128), blk, GEMM_SMEM_>>>(
        xhi, whi + OFF_IN_, wlo + OFF_IN_, b_in, nullptr,
        h_p, nullptr, nullptr, KROWS_, 64, 256);

    // 2) ln = LN(h) -> hi
    ln_k<<<KROWS_ / 8, blk>>>(h_p, g_attn, be_attn, lnhi);

    // 3) qkv = ln @ W_qkv + b_qkv -> hi (+lo for K,V cols)
    gemm_mma<3><<<dim3(12, 128), blk, GEMM_SMEM_>>>(
        lnhi, whi + OFF_QKV_, wlo + OFF_QKV_, b_qkv, nullptr,
        nullptr, qhi, qlo, KROWS_, 256, 768);

    // 4) h += window_attention(qkv)
    attn_k<<<KB_ * (KT_ / 64), blk, ATTN_SMEM_BYTES>>>(qhi, qlo, h_p);

    // 5) ln = LN(h) -> hi
    ln_k<<<KROWS_ / 8, blk>>>(h_p, g_mlp, be_mlp, lnhi);

    // 6) m1 = gelu(ln @ W1 + b1) -> hi
    gemm_mma<1><<<dim3(4, 128), blk, GEMM_SMEM_>>>(
        lnhi, whi + OFF_W1_, wlo + OFF_W1_, b1, nullptr,
        nullptr, m1hi, nullptr, KROWS_, 256, 256);

    // 7) h = h + (m1 @ W2 + b2)  (fp32 out + hi out)
    gemm_mma<2><<<dim3(4, 128), blk, GEMM_SMEM_>>>(
        m1hi, whi + OFF_W2_, wlo + OFF_W2_, b2, h_p,
        h_p, hshi, nullptr, KROWS_, 256, 256);

    // 8) out = h @ W_out + b_out
    gemm_mma<0><<<dim3(1, 128), blk, GEMM_SMEM_>>>(
        hshi, whi + OFF_OUT_, wlo + OFF_OUT_, b_out, nullptr,
        out, nullptr, nullptr, KROWS_, 256, 64);
}

// round 17
// speedup vs baseline: 1.0495x; 1.0495x over previous
#include <cuda_runtime.h>
#include <cuda_fp16.h>
#include <math.h>
#include <stdint.h>

#define KB_ 4
#define KT_ 4096
#define KDIM_ 64
#define KHID_ 256
#define KROWS_ (KB_ * KT_)   // 16384
#define HIST_ 128

// ---------------------------------------------------------------------------
// Scratch (device globals)
// ---------------------------------------------------------------------------
__device__ float g_h[KROWS_ * KHID_];
__device__ __half g_lnhi[KROWS_ * KHID_];
__device__ __half g_qkvhi[KROWS_ * 3 * KHID_];
__device__ __half g_qkvlo[KROWS_ * 3 * KHID_];
__device__ __half g_m1hi[KROWS_ * KHID_];
__device__ __half g_hshi[KROWS_ * KHID_];
__device__ __half g_xhi[KROWS_ * KDIM_];
#define OFF_IN_  0
#define OFF_QKV_ 16384
#define OFF_W1_  212992
#define OFF_W2_  278528
#define OFF_OUT_ 344064
#define WSPLIT_TOT_ 360448
#define XSPLIT_TOT_ (KROWS_ * KDIM_)
__device__ __half g_whi[WSPLIT_TOT_];
__device__ __half g_wlo[WSPLIT_TOT_];

// ---------------------------------------------------------------------------
// PTX helpers
// ---------------------------------------------------------------------------
__device__ __forceinline__ uint32_t smem_u32(const void* p) {
    uint32_t a;
    asm("{ .reg .u64 t; cvta.to.shared.u64 t, %1; cvt.u32.u64 %0, t; }"
        : "=r"(a) : "l"(p));
    return a;
}
__device__ __forceinline__ void ldsm4(uint32_t* r, uint32_t a) {
    asm volatile("ldmatrix.sync.aligned.m8n8.x4.shared.b16 {%0,%1,%2,%3}, [%4];"
        : "=r"(r[0]), "=r"(r[1]), "=r"(r[2]), "=r"(r[3]) : "r"(a));
}
__device__ __forceinline__ void ldsm4t(uint32_t* r, uint32_t a) {
    asm volatile("ldmatrix.sync.aligned.m8n8.x4.trans.shared.b16 {%0,%1,%2,%3}, [%4];"
        : "=r"(r[0]), "=r"(r[1]), "=r"(r[2]), "=r"(r[3]) : "r"(a));
}
__device__ __forceinline__ void mma_f16(float* d, const uint32_t* a,
                                        const uint32_t* b) {
    asm volatile(
        "mma.sync.aligned.m16n8k16.row.col.f32.f16.f16.f32 "
        "{%0,%1,%2,%3}, {%4,%5,%6,%7}, {%8,%9}, {%0,%1,%2,%3};"
        : "+f"(d[0]), "+f"(d[1]), "+f"(d[2]), "+f"(d[3])
        : "r"(a[0]), "r"(a[1]), "r"(a[2]), "r"(a[3]), "r"(b[0]), "r"(b[1]));
}
__device__ __forceinline__ uint32_t sw128(uint32_t off) {
    return off ^ ((off >> 3) & 0x70);
}
__device__ __forceinline__ void cp16(uint32_t smaddr, const void* g) {
    asm volatile("cp.async.cg.shared.global [%0], [%1], 16;"
                 :: "r"(smaddr), "l"(g) : "memory");
}
__device__ __forceinline__ void cp_commit() {
    asm volatile("cp.async.commit_group;" ::: "memory");
}
__device__ __forceinline__ void cp_wait0() {
    asm volatile("cp.async.wait_group 0;" ::: "memory");
}

// ---------------------------------------------------------------------------
// Merged split: 5 weights (transposed, hi+lo) + x (plain, hi only)
// ---------------------------------------------------------------------------
__global__ __launch_bounds__(256)
void wsplit_all(const float* __restrict__ x, const float* __restrict__ W_in,
                const float* __restrict__ W_qkv, const float* __restrict__ W1,
                const float* __restrict__ W2, const float* __restrict__ W_out,
                __half* __restrict__ whi, __half* __restrict__ wlo,
                __half* __restrict__ xhi)
{
    const int idx = blockIdx.x * 256 + threadIdx.x;
    if (idx >= WSPLIT_TOT_ + XSPLIT_TOT_) return;
    if (idx >= WSPLIT_TOT_) {
        const int i = idx - WSPLIT_TOT_;
        xhi[i] = __float2half_rn(x[i]);
        return;
    }
    const float* src;
    int off, N, K, local;
    if (idx < 16384)       { src = W_in;  off = OFF_IN_;  K = 64;  N = 256; local = idx; }
    else if (idx < 212992) { src = W_qkv; off = OFF_QKV_; K = 256; N = 768; local = idx - 16384; }
    else if (idx < 278528) { src = W1;    off = OFF_W1_;  K = 256; N = 256; local = idx - 212992; }
    else if (idx < 344064) { src = W2;    off = OFF_W2_;  K = 256; N = 256; local = idx - 278528; }
    else                   { src = W_out; off = OFF_OUT_; K = 256; N = 64;  local = idx - 344064; }
    const int k = local / N, n = local % N;
    const float a = src[local];
    const __half h = __float2half_rn(a);
    whi[off + (size_t)n * K + k] = h;
    wlo[off + (size_t)n * K + k] = __float2half_rn(a - __half2float(h));
}

// ---------------------------------------------------------------------------
// HMMA GEMM fp16 2-product (R15 proven config: no reg cap, 2 CTAs/SM).
// EPI: 0 bias->fp32 | 1 bias+gelu->hi | 2 bias+res->fp32+hi | 3 bias->hi+lo
// EPI==3: lo written only for n0 >= KHID_ (K/V columns)
// ---------------------------------------------------------------------------
#define GEMM_STAGE_ 32768
#define GEMM_SMEM_  (2 * GEMM_STAGE_)

__device__ __forceinline__ void gemm_stage_chunk(
    uint32_t sbst, const __half* Ahi,
    const __half* Bhi, const __half* Blo,
    int m0, int n0, int c, int K, int tid)
{
    constexpr uint32_t A_HI = 0, B_HI = 16384, B_LO = 24576;
#pragma unroll
    for (int i = 0; i < 4; i++) {
        const int u = i * 256 + tid;
        const int row = u >> 3, seg = u & 7;
        const uint32_t sw = sw128(row * 128 + seg * 16);
        cp16(sbst + A_HI + sw, &Ahi[(size_t)(m0 + row) * K + c * 64 + seg * 8]);
    }
#pragma unroll
    for (int i = 0; i < 2; i++) {
        const int u = i * 256 + tid;
        const int row = u >> 3, seg = u & 7;
        const uint32_t sw = sw128(row * 128 + seg * 16);
        const size_t gsrc = (size_t)(n0 + row) * K + c * 64 + seg * 8;
        cp16(sbst + B_HI + sw, &Bhi[gsrc]);
        cp16(sbst + B_LO + sw, &Blo[gsrc]);
    }
}

template <int EPI>
__global__ __launch_bounds__(256)
void gemm_mma(const __half* __restrict__ Ahi,
              const __half* __restrict__ Bhi, const __half* __restrict__ Blo,
              const float* __restrict__ bias, const float* __restrict__ res,
              float* __restrict__ out,
              __half* __restrict__ outhi, __half* __restrict__ outlo,
              int M, int K, int N)
{
    extern __shared__ char smp[];
    const uint32_t sb = smem_u32(smp);
    constexpr uint32_t A_HI = 0, B_HI = 16384, B_LO = 24576;

    const int tid = threadIdx.x, lane = tid & 31, w = tid >> 5;
    const int wm = w & 3, wn = w >> 2;
    const int m0 = blockIdx.y * 128, n0 = blockIdx.x * 64;

    float acc[2][4][4];
#pragma unroll
    for (int mi = 0; mi < 2; mi++)
#pragma unroll
        for (int ni = 0; ni < 4; ni++)
#pragma unroll
            for (int e = 0; e < 4; e++) acc[mi][ni][e] = 0.f;

    const int a_row_l  = lane & 15;
    const int a_kseg_l = lane >> 4;
    const int b_row_l  = ((lane >> 4) << 3) + (lane & 7);
    const int b_kseg_l = (lane >> 3) & 1;

    const int nchunks = K >> 6;

    gemm_stage_chunk(sb, Ahi, Bhi, Blo, m0, n0, 0, K, tid);
    cp_commit();

    for (int c = 0; c < nchunks; c++) {
        const uint32_t cur = sb + (uint32_t)(c & 1) * GEMM_STAGE_;
        cp_wait0();
        __syncthreads();
        if (c + 1 < nchunks) {
            gemm_stage_chunk(sb + (uint32_t)((c + 1) & 1) * GEMM_STAGE_,
                             Ahi, Bhi, Blo, m0, n0, c + 1, K, tid);
            cp_commit();
        }

#pragma unroll
        for (int ks = 0; ks < 4; ks++) {
            uint32_t ah[2][4], bh[4][2], bl[4][2];
#pragma unroll
            for (int mi = 0; mi < 2; mi++) {
                const int row = wm * 32 + mi * 16 + a_row_l;
                const uint32_t sw = sw128(row * 128 + (ks * 2 + a_kseg_l) * 16);
                ldsm4(ah[mi], cur + A_HI + sw);
            }
#pragma unroll
            for (int np = 0; np < 2; np++) {
                const int row = wn * 32 + np * 16 + b_row_l;
                const uint32_t sw = sw128(row * 128 + (ks * 2 + b_kseg_l) * 16);
                uint32_t t[4];
                ldsm4(t, cur + B_HI + sw);
                bh[np * 2][0] = t[0]; bh[np * 2][1] = t[1];
                bh[np * 2 + 1][0] = t[2]; bh[np * 2 + 1][1] = t[3];
                ldsm4(t, cur + B_LO + sw);
                bl[np * 2][0] = t[0]; bl[np * 2][1] = t[1];
                bl[np * 2 + 1][0] = t[2]; bl[np * 2 + 1][1] = t[3];
            }
#pragma unroll
            for (int mi = 0; mi < 2; mi++)
#pragma unroll
                for (int ni = 0; ni < 4; ni++)
                    mma_f16(acc[mi][ni], ah[mi], bh[ni]);
#pragma unroll
            for (int mi = 0; mi < 2; mi++)
#pragma unroll
                for (int ni = 0; ni < 4; ni++)
                    mma_f16(acc[mi][ni], ah[mi], bl[ni]);
        }
    }

    // ---- epilogue ----
    const int qrow = lane >> 2;
    const int qcol = 2 * (lane & 3);
    const bool write_lo = (EPI == 3) && (n0 >= KHID_);
#pragma unroll
    for (int mi = 0; mi < 2; mi++) {
#pragma unroll
        for (int ni = 0; ni < 4; ni++) {
            const int n = n0 + wn * 32 + ni * 8 + qcol;
            const float2 bv = *(const float2*)&bias[n];
#pragma unroll
            for (int hh = 0; hh < 2; hh++) {
                const int m = m0 + wm * 32 + mi * 16 + qrow + hh * 8;
                float2 v = make_float2(acc[mi][ni][2 * hh] + bv.x,
                                       acc[mi][ni][2 * hh + 1] + bv.y);
                if (EPI == 1) {
                    v.x = 0.5f * v.x * (1.f + erff(v.x * 0.70710678118654752f));
                    v.y = 0.5f * v.y * (1.f + erff(v.y * 0.70710678118654752f));
                }
                if (EPI == 2) {
                    float2 r = *(const float2*)&res[(size_t)m * N + n];
                    v.x += r.x; v.y += r.y;
                }
                if (EPI == 0 || EPI == 2)
                    *(float2*)&out[(size_t)m * N + n] = v;
                if (EPI != 0) {
                    __half2 h2 = __floats2half2_rn(v.x, v.y);
                    *(__half2*)&outhi[(size_t)m * N + n] = h2;
                    if (write_lo) {
                        const float rx = v.x - __half2float(__low2half(h2));
                        const float ry = v.y - __half2float(__high2half(h2));
                        *(__half2*)&outlo[(size_t)m * N + n] =
                            __floats2half2_rn(rx, ry);
                    }
                }
            }
        }
    }
}

// ---------------------------------------------------------------------------
// LayerNorm: one warp per row; outputs fp16 hi only
// ---------------------------------------------------------------------------
__global__ __launch_bounds__(256)
void ln_k(const float* __restrict__ x, const float* __restrict__ g,
          const float* __restrict__ b, __half* __restrict__ yhi)
{
    const int wid = threadIdx.x >> 5;
    const int lane = threadIdx.x & 31;
    const int row = blockIdx.x * 8 + wid;
    const float* xr = x + (size_t)row * KHID_;

    float v[8];
    float s = 0.f, s2 = 0.f;
#pragma unroll
    for (int i = 0; i < 8; i++) {
        v[i] = xr[lane + 32 * i];
        s += v[i];
        s2 += v[i] * v[i];
    }
#pragma unroll
    for (int o = 16; o; o >>= 1) {
        s += __shfl_xor_sync(0xffffffffu, s, o);
        s2 += __shfl_xor_sync(0xffffffffu, s2, o);
    }
    const float mu = s * (1.f / 256.f);
    const float var = s2 * (1.f / 256.f) - mu * mu;
    const float r = rsqrtf(var + 1e-5f);
#pragma unroll
    for (int i = 0; i < 8; i++) {
        const int d = lane + 32 * i;
        yhi[(size_t)row * KHID_ + d] =
            __float2half_rn((v[i] - mu) * r * g[d] + b[d]);
    }
}

// ---------------------------------------------------------------------------
// HMMA windowed attention, fp16 2-product; PINNED to 2 CTAs/SM.
// ---------------------------------------------------------------------------
#define ATTN_SMEM_BYTES 115712

__device__ __forceinline__ void attn_stage_q(
    uint32_t dst, const __half* qhi, int g0, int c, int tid)
{
#pragma unroll
    for (int i = 0; i < 2; i++) {
        const int u = i * 256 + tid;
        const int row = u >> 3, seg = u & 7;
        const uint32_t sw = sw128(row * 128 + seg * 16);
        cp16(dst + sw, &qhi[(size_t)(g0 + row) * 768 + c * 64 + seg * 8]);
    }
}
__device__ __forceinline__ void attn_stage_k(
    uint32_t dst_hi, const __half* qhi, const __half* qlo,
    int kg0, int c, int tid)
{
#pragma unroll
    for (int i = 0; i < 2; i++) {
        const int u = i * 256 + tid;
        const int row = u >> 3, seg = u & 7;
        const uint32_t sw = sw128(row * 128 + seg * 16);
        const size_t gsrc = (size_t)(kg0 + row) * 768 + 256 + c * 64 + seg * 8;
        cp16(dst_hi + sw, &qhi[gsrc]);
        cp16(dst_hi + 8192 + sw, &qlo[gsrc]);
    }
}
__device__ __forceinline__ void attn_stage_v(
    uint32_t vb, const __half* qhi, const __half* qlo,
    int kg0, int half, int tid)
{
#pragma unroll
    for (int i = 0; i < 4; i++) {
        const int u = i * 256 + tid;
        const int row = u >> 4, seg = u & 15;
        const int panel = seg >> 3, sp = seg & 7;
        const uint32_t sw = panel * 8192 + sw128(row * 128 + sp * 16);
        const size_t gsrc = (size_t)(kg0 + row) * 768 + 512 + half * 128 + seg * 8;
        cp16(vb + sw, &qhi[gsrc]);
        cp16(vb + 16384 + sw, &qlo[gsrc]);
    }
}

__global__ __launch_bounds__(256, 2)
void attn_k(const __half* __restrict__ qhi, const __half* __restrict__ qlo,
            float* __restrict__ h)
{
    extern __shared__ char smp[];
    const uint32_t sb = smem_u32(smp);
    constexpr uint32_t P_HI = 0, VB_ = 49152;
    float* redm = (float*)(smp + 114688);
    float* reds = (float*)(smp + 115200);

    const int tid = threadIdx.x, lane = tid & 31, w = tid >> 5;
    const int b  = blockIdx.x >> 6;
    const int qt = blockIdx.x & 63;
    const int t0 = qt * 64;
    const int g0 = b * KT_ + t0;
    const int kstart = (t0 >= HIST_) ? (t0 - HIST_) : 0;
    const int ntiles = (t0 + 64 - kstart) >> 6;
    const float scale = 0.0625f;

    const int wm = w & 3, wn = w >> 2;
    const int a_row_l  = lane & 15;
    const int a_kseg_l = lane >> 4;
    const int b_row_l  = ((lane >> 4) << 3) + (lane & 7);
    const int b_kseg_l = (lane >> 3) & 1;

    float sreg[3][4][4];
#pragma unroll
    for (int kt = 0; kt < 3; kt++)
#pragma unroll
        for (int ni = 0; ni < 4; ni++)
#pragma unroll
            for (int e = 0; e < 4; e++) sreg[kt][ni][e] = 0.f;

    attn_stage_q(sb + 0, qhi, g0, 0, tid);
    attn_stage_k(sb + 16384, qhi, qlo, b * KT_ + kstart, 0, tid);
    cp_commit();

    uint32_t kpar = 0;
    for (int c = 0; c < 4; c++) {
#pragma unroll
        for (int kt = 0; kt < 3; kt++) {
            if (kt < ntiles) {
                cp_wait0();
                __syncthreads();
                {
                    const int nkt = (kt + 1 < ntiles) ? kt + 1 : 0;
                    const int nc  = (kt + 1 < ntiles) ? c : c + 1;
                    if (nc < 4) {
                        attn_stage_k(sb + 16384 + (kpar ^ 1u) * 16384,
                                     qhi, qlo, b * KT_ + kstart + nkt * 64, nc, tid);
                        if (nkt == 0)
                            attn_stage_q(sb + (uint32_t)(nc & 1) * 8192,
                                         qhi, g0, nc, tid);
                        cp_commit();
                    }
                }
                const uint32_t qb = sb + (uint32_t)(c & 1) * 8192;
                const uint32_t kb = sb + 16384 + kpar * 16384;
#pragma unroll
                for (int ks = 0; ks < 4; ks++) {
                    uint32_t qh[4], kh[4][2], kl[4][2];
                    {
                        const int row = wm * 16 + a_row_l;
                        const uint32_t sw = sw128(row * 128 + (ks * 2 + a_kseg_l) * 16);
                        ldsm4(qh, qb + sw);
                    }
#pragma unroll
                    for (int np = 0; np < 2; np++) {
                        const int row = wn * 32 + np * 16 + b_row_l;
                        const uint32_t sw = sw128(row * 128 + (ks * 2 + b_kseg_l) * 16);
                        uint32_t t[4];
                        ldsm4(t, kb + sw);
                        kh[np * 2][0] = t[0]; kh[np * 2][1] = t[1];
                        kh[np * 2 + 1][0] = t[2]; kh[np * 2 + 1][1] = t[3];
                        ldsm4(t, kb + 8192 + sw);
                        kl[np * 2][0] = t[0]; kl[np * 2][1] = t[1];
                        kl[np * 2 + 1][0] = t[2]; kl[np * 2 + 1][1] = t[3];
                    }
#pragma unroll
                    for (int ni = 0; ni < 4; ni++)
                        mma_f16(sreg[kt][ni], qh, kh[ni]);
#pragma unroll
                    for (int ni = 0; ni < 4; ni++)
                        mma_f16(sreg[kt][ni], qh, kl[ni]);
                }
                kpar ^= 1u;
            }
        }
    }

    const int qr0 = wm * 16 + (lane >> 2);
#pragma unroll
    for (int kt = 0; kt < 3; kt++)
        if (kt < ntiles)
#pragma unroll
            for (int ni = 0; ni < 4; ni++)
#pragma unroll
                for (int e = 0; e < 4; e++) {
                    const int qrow = t0 + qr0 + 8 * (e >> 1);
                    const int key = kstart + kt * 64 + wn * 32 + ni * 8 + (lane & 3) * 2 + (e & 1);
                    const int d = qrow - key;
                    sreg[kt][ni][e] = (d >= 0 && d <= HIST_)
                                      ? sreg[kt][ni][e] * scale : -3.0e38f;
                }

    float mx[2] = {-3.0e38f, -3.0e38f};
#pragma unroll
    for (int kt = 0; kt < 3; kt++)
        if (kt < ntiles)
#pragma unroll
            for (int ni = 0; ni < 4; ni++)
#pragma unroll
                for (int e = 0; e < 4; e++)
                    mx[e >> 1] = fmaxf(mx[e >> 1], sreg[kt][ni][e]);
#pragma unroll
    for (int o = 1; o <= 2; o <<= 1) {
        mx[0] = fmaxf(mx[0], __shfl_xor_sync(0xffffffffu, mx[0], o));
        mx[1] = fmaxf(mx[1], __shfl_xor_sync(0xffffffffu, mx[1], o));
    }
    if ((lane & 3) == 0) {
        redm[qr0 * 2 + wn] = mx[0];
        redm[(qr0 + 8) * 2 + wn] = mx[1];
    }
    __syncthreads();
    attn_stage_v(sb + VB_, qhi, qlo, b * KT_ + kstart, 0, tid);
    cp_commit();

    const float M0 = fmaxf(redm[qr0 * 2], redm[qr0 * 2 + 1]);
    const float M1 = fmaxf(redm[(qr0 + 8) * 2], redm[(qr0 + 8) * 2 + 1]);
    float sum[2] = {0.f, 0.f};
#pragma unroll
    for (int kt = 0; kt < 3; kt++)
        if (kt < ntiles)
#pragma unroll
            for (int ni = 0; ni < 4; ni++)
#pragma unroll
                for (int e = 0; e < 4; e++) {
                    const float ex = __expf(sreg[kt][ni][e] - ((e >> 1) ? M1 : M0));
                    sreg[kt][ni][e] = ex;
                    sum[e >> 1] += ex;
                }
#pragma unroll
    for (int o = 1; o <= 2; o <<= 1) {
        sum[0] += __shfl_xor_sync(0xffffffffu, sum[0], o);
        sum[1] += __shfl_xor_sync(0xffffffffu, sum[1], o);
    }
    if ((lane & 3) == 0) {
        reds[qr0 * 2 + wn] = sum[0];
        reds[(qr0 + 8) * 2 + wn] = sum[1];
    }
    __syncthreads();
    const float R0 = 1.f / (reds[qr0 * 2] + reds[qr0 * 2 + 1]);
    const float R1 = 1.f / (reds[(qr0 + 8) * 2] + reds[(qr0 + 8) * 2 + 1]);

#pragma unroll
    for (int kt = 0; kt < 3; kt++)
        if (kt < ntiles)
#pragma unroll
            for (int ni = 0; ni < 4; ni++)
#pragma unroll
                for (int hh = 0; hh < 2; hh++) {
                    const float rv = hh ? R1 : R0;
                    const float p0 = sreg[kt][ni][2 * hh] * rv;
                    const float p1 = sreg[kt][ni][2 * hh + 1] * rv;
                    const int row = qr0 + 8 * hh;
                    const int col = wn * 32 + ni * 8 + (lane & 3) * 2;
                    const uint32_t sw = sw128(row * 128 + col * 2);
                    *(__half2*)(smp + P_HI + kt * 8192 + sw) =
                        __floats2half2_rn(p0, p1);
                }

    const int wm2 = w & 1, wn2 = w >> 1;
    const int R = 2 * ntiles;
    float o[2][4][4];

    for (int r = 0; r < R; r++) {
        const int half = (r < ntiles) ? 0 : 1;
        const int kt   = (r < ntiles) ? r : r - ntiles;
        const uint32_t vb = sb + VB_ + (uint32_t)(r & 1) * 32768;

        cp_wait0();
        __syncthreads();
        if (r + 1 < R) {
            const int nh = (r + 1 < ntiles) ? 0 : 1;
            const int nk = (r + 1 < ntiles) ? r + 1 : r + 1 - ntiles;
            attn_stage_v(sb + VB_ + (uint32_t)((r + 1) & 1) * 32768,
                         qhi, qlo, b * KT_ + kstart + nk * 64, nh, tid);
            cp_commit();
        }

        if (kt == 0) {
#pragma unroll
            for (int mi = 0; mi < 2; mi++)
#pragma unroll
                for (int ni = 0; ni < 4; ni++)
#pragma unroll
                    for (int e = 0; e < 4; e++) o[mi][ni][e] = 0.f;
        }

#pragma unroll
        for (int ks = 0; ks < 4; ks++) {
            uint32_t ph[2][4], vh[4][2], vl[4][2];
#pragma unroll
            for (int mi = 0; mi < 2; mi++) {
                const int row = wm2 * 32 + mi * 16 + a_row_l;
                const uint32_t sw = sw128(row * 128 + (ks * 2 + a_kseg_l) * 16);
                ldsm4(ph[mi], sb + P_HI + kt * 8192 + sw);
            }
#pragma unroll
            for (int g = 0; g < 2; g++) {
                const int dcol = wn2 * 32 + g * 16 + (lane >> 4) * 8;
                const int key = ks * 16 + (lane & 7) + ((lane >> 3) & 1) * 8;
                const int panel = dcol >> 6;
                const uint32_t sw =
                    panel * 8192 + sw128(key * 128 + (dcol & 63) * 2);
                uint32_t t[4];
                ldsm4t(t, vb + sw);
                vh[g * 2][0] = t[0]; vh[g * 2][1] = t[1];
                vh[g * 2 + 1][0] = t[2]; vh[g * 2 + 1][1] = t[3];
                ldsm4t(t, vb + 16384 + sw);
                vl[g * 2][0] = t[0]; vl[g * 2][1] = t[1];
                vl[g * 2 + 1][0] = t[2]; vl[g * 2 + 1][1] = t[3];
            }
#pragma unroll
            for (int mi = 0; mi < 2; mi++)
#pragma unroll
                for (int ni = 0; ni < 4; ni++)
                    mma_f16(o[mi][ni], ph[mi], vh[ni]);
#pragma unroll
            for (int mi = 0; mi < 2; mi++)
#pragma unroll
                for (int ni = 0; ni < 4; ni++)
                    mma_f16(o[mi][ni], ph[mi], vl[ni]);
        }

        if (kt == ntiles - 1) {
#pragma unroll
            for (int mi = 0; mi < 2; mi++)
#pragma unroll
                for (int ni = 0; ni < 4; ni++) {
                    const int col = half * 128 + wn2 * 32 + ni * 8 + (lane & 3) * 2;
#pragma unroll
                    for (int hh = 0; hh < 2; hh++) {
                        const int row = wm2 * 32 + mi * 16 + (lane >> 2) + 8 * hh;
                        float2 hv = *(const float2*)&h[(size_t)(g0 + row) * KHID_ + col];
                        hv.x += o[mi][ni][2 * hh];
                        hv.y += o[mi][ni][2 * hh + 1];
                        *(float2*)&h[(size_t)(g0 + row) * KHID_ + col] = hv;
                    }
                }
        }
    }
}

// ---------------------------------------------------------------------------
// Launch
// ---------------------------------------------------------------------------
extern "C" void kernel_launch(void* const* d_in, const int* in_sizes, int n_in,
                              void* d_out, int out_size)
{
    (void)in_sizes; (void)n_in; (void)out_size;
    const float* x       = (const float*)d_in[0];
    const float* W_in    = (const float*)d_in[1];
    const float* b_in    = (const float*)d_in[2];
    const float* W_qkv   = (const float*)d_in[3];
    const float* b_qkv   = (const float*)d_in[4];
    const float* g_attn  = (const float*)d_in[5];
    const float* be_attn = (const float*)d_in[6];
    const float* g_mlp   = (const float*)d_in[7];
    const float* be_mlp  = (const float*)d_in[8];
    const float* W1      = (const float*)d_in[9];
    const float* b1      = (const float*)d_in[10];
    const float* W2      = (const float*)d_in[11];
    const float* b2      = (const float*)d_in[12];
    const float* W_out   = (const float*)d_in[13];
    const float* b_out   = (const float*)d_in[14];
    float* out = (float*)d_out;

    float* h_p;
    __half *whi, *wlo, *xhi, *lnhi, *qhi, *qlo, *m1hi, *hshi;
    cudaGetSymbolAddress((void**)&h_p, g_h);
    cudaGetSymbolAddress((void**)&whi, g_whi);
    cudaGetSymbolAddress((void**)&wlo, g_wlo);
    cudaGetSymbolAddress((void**)&xhi, g_xhi);
    cudaGetSymbolAddress((void**)&lnhi, g_lnhi);
    cudaGetSymbolAddress((void**)&qhi, g_qkvhi);
    cudaGetSymbolAddress((void**)&qlo, g_qkvlo);
    cudaGetSymbolAddress((void**)&m1hi, g_m1hi);
    cudaGetSymbolAddress((void**)&hshi, g_hshi);

    cudaFuncSetAttribute((const void*)attn_k,
                         cudaFuncAttributeMaxDynamicSharedMemorySize, ATTN_SMEM_BYTES);
    cudaFuncSetAttribute((const void*)gemm_mma<0>,
                         cudaFuncAttributeMaxDynamicSharedMemorySize, GEMM_SMEM_);
    cudaFuncSetAttribute((const void*)gemm_mma<1>,
                         cudaFuncAttributeMaxDynamicSharedMemorySize, GEMM_SMEM_);
    cudaFuncSetAttribute((const void*)gemm_mma<2>,
                         cudaFuncAttributeMaxDynamicSharedMemorySize, GEMM_SMEM_);
    cudaFuncSetAttribute((const void*)gemm_mma<3>,
                         cudaFuncAttributeMaxDynamicSharedMemorySize, GEMM_SMEM_);

    const dim3 blk(256);

    // 0) split everything once
    wsplit_all<<<(WSPLIT_TOT_ + XSPLIT_TOT_ + 255) / 256, blk>>>(
        x, W_in, W_qkv, W1, W2, W_out, whi, wlo, xhi);

    // 1) h = x @ W_in + b_in
    gemm_mma<0><<<dim3(4, 128), blk, GEMM_SMEM_>>>(
        xhi, whi + OFF_IN_, wlo + OFF_IN_, b_in, nullptr,
        h_p, nullptr, nullptr, KROWS_, 64, 256);

    // 2) ln = LN(h) -> hi
    ln_k<<<KROWS_ / 8, blk>>>(h_p, g_attn, be_attn, lnhi);

    // 3) qkv = ln @ W_qkv + b_qkv -> hi (+lo for K,V cols)
    gemm_mma<3><<<dim3(12, 128), blk, GEMM_SMEM_>>>(
        lnhi, whi + OFF_QKV_, wlo + OFF_QKV_, b_qkv, nullptr,
        nullptr, qhi, qlo, KROWS_, 256, 768);

    // 4) h += window_attention(qkv)
    attn_k<<<KB_ * (KT_ / 64), blk, ATTN_SMEM_BYTES>>>(qhi, qlo, h_p);

    // 5) ln = LN(h) -> hi
    ln_k<<<KROWS_ / 8, blk>>>(h_p, g_mlp, be_mlp, lnhi);

    // 6) m1 = gelu(ln @ W1 + b1) -> hi
    gemm_mma<1><<<dim3(4, 128), blk, GEMM_SMEM_>>>(
        lnhi, whi + OFF_W1_, wlo + OFF_W1_, b1, nullptr,
        nullptr, m1hi, nullptr, KROWS_, 256, 256);

    // 7) h = h + (m1 @ W2 + b2)  (fp32 out + hi out)
    gemm_mma<2><<<dim3(4, 128), blk, GEMM_SMEM_>>>(
        m1hi, whi + OFF_W2_, wlo + OFF_W2_, b2, h_p,
        h_p, hshi, nullptr, KROWS_, 256, 256);

    // 8) out = h @ W_out + b_out
    gemm_mma<0><<<dim3(1, 128), blk, GEMM_SMEM_>>>(
        hshi, whi + OFF_OUT_, wlo + OFF_OUT_, b_out, nullptr,
        out, nullptr, nullptr, KROWS_, 256, 64);
}